// round 8
// baseline (speedup 1.0000x reference)
#include <cuda_runtime.h>
#include <cuda_bf16.h>

#define THREADS 256
#define ROWS 8                        // edges per group-tile
#define XPITCH 132                    // fp32 words per staged edge row (4-bank pad)
#define SLOT (ROWS * XPITCH)          // floats per slot (1056)
#define NBUF 8
#define GROUPS 2                      // edge groups per CTA (4 warps each)

__device__ int g_idx_is64;

static __device__ __forceinline__ unsigned int pack_bf16x2(float lo, float hi) {
    __nv_bfloat162 hh = __float22bfloat162_rn(make_float2(lo, hi));
    return *reinterpret_cast<unsigned int*>(&hh);
}

// ---------------- prep: zero output + detect index dtype ----------------
__global__ void prep_kernel(float4* out, int n4, const unsigned int* idxw, int n_pairs) {
    int i = blockIdx.x * blockDim.x + threadIdx.x;
    int stride = gridDim.x * blockDim.x;
    for (; i < n4; i += stride) out[i] = make_float4(0.f, 0.f, 0.f, 0.f);
    if (blockIdx.x == 0) {
        __shared__ unsigned int acc;
        if (threadIdx.x == 0) acc = 0u;
        __syncthreads();
        unsigned int v = 0u;
        for (int j = threadIdx.x; j < n_pairs; j += blockDim.x) v |= idxw[2 * j + 1];
        atomicOr(&acc, v);
        __syncthreads();
        if (threadIdx.x == 0) g_idx_is64 = (acc == 0u) ? 1 : 0;
    }
}

// ---------------- fused gate-GEMM + register scatter, 4-warp group pipelines ----------------
__global__ __launch_bounds__(THREADS, 2)
void fused_gate_scatter(const float* __restrict__ x,
                        const float* __restrict__ Wg,
                        const float* __restrict__ lparam,
                        const void* __restrict__ index,
                        float* __restrict__ out,
                        long long E, int num_tiles)
{
    extern __shared__ char smem_raw[];
    float* Xsm = reinterpret_cast<float*>(smem_raw);                 // [GROUPS][NBUF][ROWS][XPITCH]
    long long* Nsm = reinterpret_cast<long long*>(Xsm + GROUPS * NBUF * SLOT); // [GROUPS][NBUF][ROWS]

    const int tid  = threadIdx.x;
    const int wid  = tid >> 5;
    const int lane = tid & 31;
    const int g    = lane >> 2;      // 0..7 : edge row within group-tile
    const int q    = lane & 3;       // 0..3
    const int grp  = wid >> 2;       // 0..1 : edge group
    const int qt   = wid & 3;        // 0..3 : gate-col quarter (32 cols)

    const int   is64 = g_idx_is64;
    const float lp   = fabsf(__ldg(lparam));

    float* grpBuf = Xsm + grp * (NBUF * SLOT);
    long long* NsmG = Nsm + grp * (NBUF * ROWS);
    int* NsmG32 = reinterpret_cast<int*>(NsmG);

    // ---- persistent B fragments: cols n = qt*32 + nt*8 + g, nt=0..3 ----
    unsigned int Breg[4][4][2];
    #pragma unroll
    for (int nt = 0; nt < 4; nt++) {
        const int n = qt * 32 + nt * 8 + g;
        #pragma unroll
        for (int ks = 0; ks < 4; ks++) {
            const int k = ks * 16 + q * 2;
            float2 w0 = __ldg(reinterpret_cast<const float2*>(Wg + n * 64 + k));
            float2 w1 = __ldg(reinterpret_cast<const float2*>(Wg + n * 64 + k + 8));
            Breg[nt][ks][0] = pack_bf16x2(w0.x, w0.y);
            Breg[nt][ks][1] = pack_bf16x2(w1.x, w1.y);
        }
    }

    const unsigned int xbuf_u32 = (unsigned int)__cvta_generic_to_shared(grpBuf);
    const unsigned int nbuf_u32 = (unsigned int)__cvta_generic_to_shared(NsmG);

    // stage one 8-edge tile-let; warp qt stages rows qt*2, qt*2+1
    auto stage = [&](int t, int slot) {
        const long long ebase = (long long)t * ROWS;
        #pragma unroll
        for (int p = 0; p < 2; p++) {
            const int row = qt * 2 + p;
            long long e = ebase + row;
            if (e < E) {
                unsigned int dst = xbuf_u32 + (unsigned)((slot * SLOT + row * XPITCH + lane * 4) * 4);
                const float* src = x + e * 128 + lane * 4;
                asm volatile("cp.async.cg.shared.global [%0], [%1], 16;" :: "r"(dst), "l"(src));
            }
        }
        if (qt == 0) {
            if (ebase + ROWS <= E) {
                if (is64) {
                    if (lane < 4) {   // 8 * 8B = 64B
                        unsigned int dst = nbuf_u32 + (unsigned)(slot * 64 + lane * 16);
                        const char* src = (const char*)index + ebase * 8 + lane * 16;
                        asm volatile("cp.async.ca.shared.global [%0], [%1], 16;" :: "r"(dst), "l"(src));
                    }
                } else {
                    if (lane < 2) {   // 8 * 4B = 32B
                        unsigned int dst = nbuf_u32 + (unsigned)(slot * 64 + lane * 16);
                        const char* src = (const char*)index + ebase * 4 + lane * 16;
                        asm volatile("cp.async.ca.shared.global [%0], [%1], 16;" :: "r"(dst), "l"(src));
                    }
                }
            } else {  // partial tail tile-let: guarded direct loads
                if (lane < ROWS && ebase + lane < E) {
                    if (is64) NsmG[slot * ROWS + lane] = ((const long long*)index)[ebase + lane];
                    else      NsmG32[slot * ROWS * 2 + lane] = ((const int*)index)[ebase + lane];
                }
            }
        }
    };

    const int S  = (int)gridDim.x * GROUPS;
    const int pg = (int)blockIdx.x * GROUPS + grp;

    // ---- prologue: prime NBUF-1 slots ----
    #pragma unroll
    for (int j = 0; j < NBUF - 1; j++) {
        int t = pg + j * S;
        if (t < num_tiles) stage(t, j);
        asm volatile("cp.async.commit_group;");
    }

    int c = 0;
    for (int tcur = pg; tcur < num_tiles; tcur += S, c++) {
        asm volatile("cp.async.wait_group %0;" :: "n"(NBUF - 2));     // own slot c complete
        asm volatile("bar.sync %0, 128;" :: "r"(grp + 1) : "memory"); // group mates too; restage target free
        int tpre = tcur + (NBUF - 1) * S;
        if (tpre < num_tiles) stage(tpre, (c + NBUF - 1) & (NBUF - 1));
        asm volatile("cp.async.commit_group;");

        const int slot = c & (NBUF - 1);
        const long long ebase = (long long)tcur * ROWS;
        const bool valid = (ebase + g < E);
        const float* Xrow = grpBuf + slot * SLOT + g * XPITCH;

        long long nd = 0;
        if (valid)
            nd = is64 ? NsmG[slot * ROWS + g]
                      : (long long)NsmG32[slot * ROWS * 2 + g];

        // ---- MMA with A-fragments kept for the epilogue ----
        float2 F0[4], F1[4], F2[4], F3[4];
        float acc[4][4];
        #pragma unroll
        for (int nt = 0; nt < 4; nt++) {
            acc[nt][0] = 0.f; acc[nt][1] = 0.f; acc[nt][2] = 0.f; acc[nt][3] = 0.f;
        }

        #pragma unroll
        for (int ks = 0; ks < 4; ks++) {
            const int kb = ks * 16 + q * 2;
            F0[ks] = *reinterpret_cast<const float2*>(Xrow + kb);          // patch0, col kb
            F1[ks] = *reinterpret_cast<const float2*>(Xrow + 64 + kb);     // patch1, col kb
            F2[ks] = *reinterpret_cast<const float2*>(Xrow + kb + 8);      // patch0, col kb+8
            F3[ks] = *reinterpret_cast<const float2*>(Xrow + 64 + kb + 8); // patch1, col kb+8
            unsigned int a0 = pack_bf16x2(F0[ks].x, F0[ks].y);
            unsigned int a1 = pack_bf16x2(F1[ks].x, F1[ks].y);
            unsigned int a2 = pack_bf16x2(F2[ks].x, F2[ks].y);
            unsigned int a3 = pack_bf16x2(F3[ks].x, F3[ks].y);
            #pragma unroll
            for (int nt = 0; nt < 4; nt++) {
                asm volatile(
                    "mma.sync.aligned.m16n8k16.row.col.f32.bf16.bf16.f32 "
                    "{%0,%1,%2,%3}, {%4,%5,%6,%7}, {%8,%9}, {%0,%1,%2,%3};"
                    : "+f"(acc[nt][0]), "+f"(acc[nt][1]),
                      "+f"(acc[nt][2]), "+f"(acc[nt][3])
                    : "r"(a0), "r"(a1), "r"(a2), "r"(a3),
                      "r"(Breg[nt][ks][0]), "r"(Breg[nt][ks][1]));
            }
        }

        // ---- epilogue + direct register scatter ----
        // output col o = qt*32 + nt*8 + q*2 ; patch-dim index d = o & 63
        // m = d/8 = (qt&1)*4 + nt ; ks = m>>1 ; hi = m&1 ; pass-through patch = qt>>1
        float* pbase = out + nd * 128 + qt * 32 + q * 2;
        #pragma unroll
        for (int nt = 0; nt < 4; nt++) {
            const int m  = ((qt & 1) << 2) + nt;
            const int ks = m >> 1;
            float2 e0 = (m & 1) ? F2[ks] : F0[ks];    // patch0 e at col d
            float2 e1 = (m & 1) ? F3[ks] : F1[ks];    // patch1 e at col d
            float sx = e0.x * __saturatef(acc[nt][0]) + e1.x * __saturatef(acc[nt][2]);
            float sy = e0.y * __saturatef(acc[nt][1]) + e1.y * __saturatef(acc[nt][3]);
            float bx = (qt >> 1) ? e1.x : e0.x;       // pass-through e[edge, o]
            float by = (qt >> 1) ? e1.y : e0.y;
            float vx = fmaf(lp, sx, bx);
            float vy = fmaf(lp, sy, by);
            if (valid) {
                asm volatile("red.global.add.v2.f32 [%0], {%1, %2};"
                             :: "l"(pbase + nt * 8), "f"(vx), "f"(vy) : "memory");
            }
        }
    }
}

// ---------------- launch ----------------
extern "C" void kernel_launch(void* const* d_in, const int* in_sizes, int n_in,
                              void* d_out, int out_size) {
    const float* x   = (const float*)d_in[0];
    const float* Wg  = (const float*)d_in[1];
    const float* lp  = (const float*)d_in[2];
    const void*  idx = d_in[3];

    long long E = (long long)in_sizes[0] / 128;
    int tiles = (int)((E + ROWS - 1) / ROWS);

    int dev = 0; cudaGetDevice(&dev);
    int sms = 148;
    cudaDeviceGetAttribute(&sms, cudaDevAttrMultiProcessorCount, dev);

    // prep: zero output + detect index dtype (single launch)
    int n4 = out_size / 4;
    long long npairs64 = E / 2; int npairs = npairs64 > 4096 ? 4096 : (int)npairs64;
    int zgrid = (n4 + 255) / 256;
    prep_kernel<<<zgrid, 256>>>((float4*)d_out, n4, (const unsigned int*)idx, npairs);

    size_t smem = (size_t)GROUPS * NBUF * SLOT * 4      // X rings
                + (size_t)GROUPS * NBUF * ROWS * 8;     // node rings
    cudaFuncSetAttribute(fused_gate_scatter,
                         cudaFuncAttributeMaxDynamicSharedMemorySize, (int)smem);
    int grid = 2 * sms;
    int maxg = (tiles + GROUPS - 1) / GROUPS;
    if (grid > maxg) grid = maxg;
    fused_gate_scatter<<<grid, THREADS, smem>>>(x, Wg, lp, idx, (float*)d_out, E, tiles);
}

// round 9
// speedup vs baseline: 2.4343x; 2.4343x over previous
#include <cuda_runtime.h>
#include <cuda_bf16.h>

#define THREADS 192
#define ROWS 8                        // edges per pair-tile
#define XPITCH 132                    // fp32 words per staged edge row (4-bank pad)
#define SLOT (ROWS * XPITCH)          // floats per slot (1056)
#define NBUF 8                        // ring slots
#define AHEAD 4                       // stage-ahead distance (tiles)
#define BLK 4                         // sync cadence (iterations per barrier)

__device__ int g_idx_is64;

static __device__ __forceinline__ unsigned int pack_bf16x2(float lo, float hi) {
    __nv_bfloat162 hh = __float22bfloat162_rn(make_float2(lo, hi));
    return *reinterpret_cast<unsigned int*>(&hh);
}

// ---------------- prep: zero output + detect index dtype ----------------
__global__ void prep_kernel(float4* out, int n4, const unsigned int* idxw, int n_pairs) {
    int i = blockIdx.x * blockDim.x + threadIdx.x;
    int stride = gridDim.x * blockDim.x;
    for (; i < n4; i += stride) out[i] = make_float4(0.f, 0.f, 0.f, 0.f);
    if (blockIdx.x == 0) {
        __shared__ unsigned int acc;
        if (threadIdx.x == 0) acc = 0u;
        __syncthreads();
        unsigned int v = 0u;
        for (int j = threadIdx.x; j < n_pairs; j += blockDim.x) v |= idxw[2 * j + 1];
        atomicOr(&acc, v);
        __syncthreads();
        if (threadIdx.x == 0) g_idx_is64 = (acc == 0u) ? 1 : 0;
    }
}

// ---------------- fused gate-GEMM + register scatter, amortized-sync pipelines ----------------
__global__ __launch_bounds__(THREADS, 2)
void fused_gate_scatter(const float* __restrict__ x,
                        const float* __restrict__ Wg,
                        const float* __restrict__ lparam,
                        const void* __restrict__ index,
                        float* __restrict__ out,
                        long long E, int num_tiles)
{
    extern __shared__ char smem_raw[];
    float* Xsm = reinterpret_cast<float*>(smem_raw);                 // [3][NBUF][ROWS][XPITCH]
    long long* Nsm = reinterpret_cast<long long*>(Xsm + 3 * NBUF * SLOT); // [3][NBUF][ROWS]

    const int tid  = threadIdx.x;
    const int wid  = tid >> 5;
    const int lane = tid & 31;
    const int g    = lane >> 2;      // 0..7 : edge row within pair-tile
    const int q    = lane & 3;       // 0..3
    const int pair = wid >> 1;       // 0..2
    const int h    = wid & 1;        // 0/1 : gate-col half

    const int   is64 = g_idx_is64;
    const float lp   = fabsf(__ldg(lparam));

    float* pairBuf = Xsm + pair * (NBUF * SLOT);
    long long* NsmP = Nsm + pair * (NBUF * ROWS);
    int* NsmP32 = reinterpret_cast<int*>(NsmP);

    // ---- persistent B fragments: cols n = h*64 + nt*8 + g ----
    unsigned int Breg[8][4][2];
    #pragma unroll
    for (int nt = 0; nt < 8; nt++) {
        const int n = h * 64 + nt * 8 + g;
        #pragma unroll
        for (int ks = 0; ks < 4; ks++) {
            const int k = ks * 16 + q * 2;
            float2 w0 = __ldg(reinterpret_cast<const float2*>(Wg + n * 64 + k));
            float2 w1 = __ldg(reinterpret_cast<const float2*>(Wg + n * 64 + k + 8));
            Breg[nt][ks][0] = pack_bf16x2(w0.x, w0.y);
            Breg[nt][ks][1] = pack_bf16x2(w1.x, w1.y);
        }
    }

    const unsigned int xbuf_u32 = (unsigned int)__cvta_generic_to_shared(pairBuf);
    const unsigned int nbuf_u32 = (unsigned int)__cvta_generic_to_shared(NsmP);

    // stage one 8-edge tile-let into slot; warp h stages rows h*4 .. h*4+3
    auto stage = [&](int t, int slot) {
        const long long ebase = (long long)t * ROWS;
        #pragma unroll
        for (int p = 0; p < 4; p++) {
            const int row = h * 4 + p;
            long long e = ebase + row;
            if (e < E) {
                unsigned int dst = xbuf_u32 + (unsigned)((slot * SLOT + row * XPITCH + lane * 4) * 4);
                const float* src = x + e * 128 + lane * 4;
                asm volatile("cp.async.cg.shared.global [%0], [%1], 16;" :: "r"(dst), "l"(src));
            }
        }
        // index staging only for full tiles; tail handled by direct LDG at consume
        if (h == 0 && ebase + ROWS <= E) {
            if (is64) {
                if (lane < 4) {   // 8 * 8B = 64B
                    unsigned int dst = nbuf_u32 + (unsigned)(slot * 64 + lane * 16);
                    const char* src = (const char*)index + ebase * 8 + lane * 16;
                    asm volatile("cp.async.ca.shared.global [%0], [%1], 16;" :: "r"(dst), "l"(src));
                }
            } else {
                if (lane < 2) {   // 8 * 4B = 32B
                    unsigned int dst = nbuf_u32 + (unsigned)(slot * 64 + lane * 16);
                    const char* src = (const char*)index + ebase * 4 + lane * 16;
                    asm volatile("cp.async.ca.shared.global [%0], [%1], 16;" :: "r"(dst), "l"(src));
                }
            }
        }
    };

    // consume one tile-let from slot
    auto consume = [&](int t, int slot) {
        const long long ebase = (long long)t * ROWS;
        const long long eg = ebase + g;
        const bool valid = (eg < E);
        const float* Xrow = pairBuf + slot * SLOT + g * XPITCH;

        long long nd = 0;
        if (valid) {
            if (ebase + ROWS <= E)
                nd = is64 ? NsmP[slot * ROWS + g]
                          : (long long)NsmP32[slot * ROWS * 2 + g];
            else
                nd = is64 ? ((const long long*)index)[eg]
                          : (long long)((const int*)index)[eg];
        }

        float2 F0[4], F1[4], F2[4], F3[4];
        float acc[8][4];
        #pragma unroll
        for (int nt = 0; nt < 8; nt++) {
            acc[nt][0] = 0.f; acc[nt][1] = 0.f; acc[nt][2] = 0.f; acc[nt][3] = 0.f;
        }

        #pragma unroll
        for (int ks = 0; ks < 4; ks++) {
            const int kb = ks * 16 + q * 2;
            F0[ks] = *reinterpret_cast<const float2*>(Xrow + kb);          // patch0, col kb
            F1[ks] = *reinterpret_cast<const float2*>(Xrow + 64 + kb);     // patch1, col kb
            F2[ks] = *reinterpret_cast<const float2*>(Xrow + kb + 8);      // patch0, col kb+8
            F3[ks] = *reinterpret_cast<const float2*>(Xrow + 64 + kb + 8); // patch1, col kb+8
            unsigned int a0 = pack_bf16x2(F0[ks].x, F0[ks].y);
            unsigned int a1 = pack_bf16x2(F1[ks].x, F1[ks].y);
            unsigned int a2 = pack_bf16x2(F2[ks].x, F2[ks].y);
            unsigned int a3 = pack_bf16x2(F3[ks].x, F3[ks].y);
            #pragma unroll
            for (int nt = 0; nt < 8; nt++) {
                asm volatile(
                    "mma.sync.aligned.m16n8k16.row.col.f32.bf16.bf16.f32 "
                    "{%0,%1,%2,%3}, {%4,%5,%6,%7}, {%8,%9}, {%0,%1,%2,%3};"
                    : "+f"(acc[nt][0]), "+f"(acc[nt][1]),
                      "+f"(acc[nt][2]), "+f"(acc[nt][3])
                    : "r"(a0), "r"(a1), "r"(a2), "r"(a3),
                      "r"(Breg[nt][ks][0]), "r"(Breg[nt][ks][1]));
            }
        }

        float* pbase = out + nd * 128 + h * 64 + q * 2;
        #pragma unroll
        for (int nt = 0; nt < 8; nt++) {
            const int ks = nt >> 1;
            float2 e0 = (nt & 1) ? F2[ks] : F0[ks];   // patch0 e at col 8*nt+q*2
            float2 e1 = (nt & 1) ? F3[ks] : F1[ks];   // patch1 e
            float sx = e0.x * __saturatef(acc[nt][0]) + e1.x * __saturatef(acc[nt][2]);
            float sy = e0.y * __saturatef(acc[nt][1]) + e1.y * __saturatef(acc[nt][3]);
            float bx = h ? e1.x : e0.x;               // pass-through e[edge, h*64+col]
            float by = h ? e1.y : e0.y;
            float vx = fmaf(lp, sx, bx);
            float vy = fmaf(lp, sy, by);
            if (valid) {
                asm volatile("red.global.add.v2.f32 [%0], {%1, %2};"
                             :: "l"(pbase + nt * 8), "f"(vx), "f"(vy) : "memory");
            }
        }
    };

    const int S  = (int)gridDim.x * 3;
    const int pg = (int)blockIdx.x * 3 + pair;

    // ---- prologue: prime AHEAD slots ----
    #pragma unroll
    for (int j = 0; j < AHEAD; j++) {
        int t = pg + j * S;
        if (t < num_tiles) stage(t, j);
        asm volatile("cp.async.commit_group;");
    }

    int c = 0;
    for (long long tbase = pg; tbase < num_tiles; tbase += (long long)BLK * S, c += BLK) {
        // sync point (once per BLK iterations): all outstanding stages landed,
        // both warps of the pair past the previous block.
        asm volatile("cp.async.wait_group 0;");
        asm volatile("bar.sync %0, 64;" :: "r"(pair + 1) : "memory");

        #pragma unroll
        for (int u = 0; u < BLK; u++) {
            long long t64 = tbase + (long long)u * S;
            if (t64 < num_tiles) {
                int t = (int)t64;
                int cc = c + u;
                long long tp = t64 + (long long)AHEAD * S;
                if (tp < num_tiles) stage((int)tp, (cc + AHEAD) & (NBUF - 1));
                asm volatile("cp.async.commit_group;");
                consume(t, cc & (NBUF - 1));
            }
        }
    }
}

// ---------------- launch ----------------
extern "C" void kernel_launch(void* const* d_in, const int* in_sizes, int n_in,
                              void* d_out, int out_size) {
    const float* x   = (const float*)d_in[0];
    const float* Wg  = (const float*)d_in[1];
    const float* lp  = (const float*)d_in[2];
    const void*  idx = d_in[3];

    long long E = (long long)in_sizes[0] / 128;
    int tiles = (int)((E + ROWS - 1) / ROWS);

    int dev = 0; cudaGetDevice(&dev);
    int sms = 148;
    cudaDeviceGetAttribute(&sms, cudaDevAttrMultiProcessorCount, dev);

    // prep: zero output + detect index dtype (single launch)
    int n4 = out_size / 4;
    long long npairs64 = E / 2; int npairs = npairs64 > 4096 ? 4096 : (int)npairs64;
    int zgrid = (n4 + 255) / 256;
    prep_kernel<<<zgrid, 256>>>((float4*)d_out, n4, (const unsigned int*)idx, npairs);

    size_t smem = (size_t)3 * NBUF * SLOT * 4       // X rings (3 pairs)
                + (size_t)3 * NBUF * ROWS * 8;      // node rings
    cudaFuncSetAttribute(fused_gate_scatter,
                         cudaFuncAttributeMaxDynamicSharedMemorySize, (int)smem);
    int grid = 2 * sms;
    int maxg = (tiles + 2) / 3;
    if (grid > maxg) grid = maxg;
    fused_gate_scatter<<<grid, THREADS, smem>>>(x, Wg, lp, idx, (float*)d_out, E, tiles);
}

// round 10
// speedup vs baseline: 2.4835x; 1.0202x over previous
#include <cuda_runtime.h>
#include <cuda_bf16.h>

#define THREADS 128
#define PAIRS 2                       // warp pairs per CTA
#define ROWS 8                        // edges per pair-tile
#define XPITCH 132                    // fp32 words per staged edge row (4-bank pad)
#define SLOT (ROWS * XPITCH)          // floats per slot (1056)
#define NBUF 4                        // ring slots per pair

__device__ int g_idx_is64;

static __device__ __forceinline__ unsigned int pack_bf16x2(float lo, float hi) {
    __nv_bfloat162 hh = __float22bfloat162_rn(make_float2(lo, hi));
    return *reinterpret_cast<unsigned int*>(&hh);
}
static __device__ __forceinline__ float2 unpack_bf16x2(unsigned int u) {
    float2 r;
    r.x = __uint_as_float(u << 16);
    r.y = __uint_as_float(u & 0xffff0000u);
    return r;
}

// ---------------- prep: zero output + detect index dtype ----------------
__global__ void prep_kernel(float4* out, int n4, const unsigned int* idxw, int n_pairs) {
    int i = blockIdx.x * blockDim.x + threadIdx.x;
    int stride = gridDim.x * blockDim.x;
    for (; i < n4; i += stride) out[i] = make_float4(0.f, 0.f, 0.f, 0.f);
    if (blockIdx.x == 0) {
        __shared__ unsigned int acc;
        if (threadIdx.x == 0) acc = 0u;
        __syncthreads();
        unsigned int v = 0u;
        for (int j = threadIdx.x; j < n_pairs; j += blockDim.x) v |= idxw[2 * j + 1];
        atomicOr(&acc, v);
        __syncthreads();
        if (threadIdx.x == 0) g_idx_is64 = (acc == 0u) ? 1 : 0;
    }
}

// ---------------- fused gate-GEMM + register scatter ----------------
__global__ __launch_bounds__(THREADS, 4)
void fused_gate_scatter(const float* __restrict__ x,
                        const float* __restrict__ Wg,
                        const float* __restrict__ lparam,
                        const void* __restrict__ index,
                        float* __restrict__ out,
                        long long E, int num_tiles)
{
    extern __shared__ char smem_raw[];
    float* Xsm = reinterpret_cast<float*>(smem_raw);                 // [PAIRS][NBUF][ROWS][XPITCH]
    long long* Nsm = reinterpret_cast<long long*>(Xsm + PAIRS * NBUF * SLOT); // [PAIRS][NBUF][ROWS]

    const int tid  = threadIdx.x;
    const int wid  = tid >> 5;
    const int lane = tid & 31;
    const int g    = lane >> 2;      // 0..7 : edge row within pair-tile
    const int q    = lane & 3;       // 0..3
    const int pair = wid >> 1;       // 0..1
    const int h    = wid & 1;        // 0/1 : gate-col half

    const int   is64 = g_idx_is64;
    const float lp   = fabsf(__ldg(lparam));

    float* pairBuf = Xsm + pair * (NBUF * SLOT);
    long long* NsmP = Nsm + pair * (NBUF * ROWS);
    int* NsmP32 = reinterpret_cast<int*>(NsmP);

    // ---- persistent B fragments: cols n = h*64 + m*8 + g, m = 0..7 ----
    unsigned int Breg[8][4][2];
    #pragma unroll
    for (int m = 0; m < 8; m++) {
        const int n = h * 64 + m * 8 + g;
        #pragma unroll
        for (int ks = 0; ks < 4; ks++) {
            const int k = ks * 16 + q * 2;
            float2 w0 = __ldg(reinterpret_cast<const float2*>(Wg + n * 64 + k));
            float2 w1 = __ldg(reinterpret_cast<const float2*>(Wg + n * 64 + k + 8));
            Breg[m][ks][0] = pack_bf16x2(w0.x, w0.y);
            Breg[m][ks][1] = pack_bf16x2(w1.x, w1.y);
        }
    }

    const unsigned int xbuf_u32 = (unsigned int)__cvta_generic_to_shared(pairBuf);
    const unsigned int nbuf_u32 = (unsigned int)__cvta_generic_to_shared(NsmP);

    // stage one 8-edge tile-let into slot; warp h stages rows h*4 .. h*4+3
    auto stage = [&](int t, int slot) {
        const long long ebase = (long long)t * ROWS;
        #pragma unroll
        for (int p = 0; p < 4; p++) {
            const int row = h * 4 + p;
            long long e = ebase + row;
            if (e < E) {
                unsigned int dst = xbuf_u32 + (unsigned)((slot * SLOT + row * XPITCH + lane * 4) * 4);
                const float* src = x + e * 128 + lane * 4;
                asm volatile("cp.async.cg.shared.global [%0], [%1], 16;" :: "r"(dst), "l"(src));
            }
        }
        // index staging only for full tiles; tail handled by direct LDG at consume
        if (h == 0 && ebase + ROWS <= E) {
            if (is64) {
                if (lane < 4) {
                    unsigned int dst = nbuf_u32 + (unsigned)(slot * 64 + lane * 16);
                    const char* src = (const char*)index + ebase * 8 + lane * 16;
                    asm volatile("cp.async.ca.shared.global [%0], [%1], 16;" :: "r"(dst), "l"(src));
                }
            } else {
                if (lane < 2) {
                    unsigned int dst = nbuf_u32 + (unsigned)(slot * 64 + lane * 16);
                    const char* src = (const char*)index + ebase * 4 + lane * 16;
                    asm volatile("cp.async.ca.shared.global [%0], [%1], 16;" :: "r"(dst), "l"(src));
                }
            }
        }
    };

    const int S  = (int)gridDim.x * PAIRS;
    const int pg = (int)blockIdx.x * PAIRS + pair;

    // ---- prologue: prime NBUF-1 slots ----
    #pragma unroll
    for (int j = 0; j < NBUF - 1; j++) {
        int t = pg + j * S;
        if (t < num_tiles) stage(t, j);
        asm volatile("cp.async.commit_group;");
    }

    int c = 0;
    for (int tcur = pg; tcur < num_tiles; tcur += S, c++) {
        asm volatile("cp.async.wait_group %0;" :: "n"(NBUF - 2));     // own slot c complete
        asm volatile("bar.sync %0, 64;" :: "r"(pair + 1) : "memory"); // partner done with restage target
        int tpre = tcur + (NBUF - 1) * S;
        if (tpre < num_tiles) stage(tpre, (c + NBUF - 1) & (NBUF - 1));
        asm volatile("cp.async.commit_group;");

        const int slot = c & (NBUF - 1);
        const long long ebase = (long long)tcur * ROWS;
        const long long eg = ebase + g;
        const bool valid = (eg < E);
        const float* Xrow = pairBuf + slot * SLOT + g * XPITCH;

        long long nd = 0;
        if (valid) {
            if (ebase + ROWS <= E)
                nd = is64 ? NsmP[slot * ROWS + g]
                          : (long long)NsmP32[slot * ROWS * 2 + g];
            else
                nd = is64 ? ((const long long*)index)[eg]
                          : (long long)((const int*)index)[eg];
        }

        // ---- load + convert A; keep bf16 (both patches) + fp32 of patch h ----
        unsigned int ap0[4], ap1[4], ap2[4], ap3[4];   // packed bf16: p0@kb, p1@kb, p0@kb+8, p1@kb+8
        float2 Fh_lo[4], Fh_hi[4];                     // fp32 of patch h: cols kb, kb+8
        #pragma unroll
        for (int ks = 0; ks < 4; ks++) {
            const int kb = ks * 16 + q * 2;
            float2 f0 = *reinterpret_cast<const float2*>(Xrow + kb);
            float2 f1 = *reinterpret_cast<const float2*>(Xrow + 64 + kb);
            float2 f2 = *reinterpret_cast<const float2*>(Xrow + kb + 8);
            float2 f3 = *reinterpret_cast<const float2*>(Xrow + 64 + kb + 8);
            ap0[ks] = pack_bf16x2(f0.x, f0.y);
            ap1[ks] = pack_bf16x2(f1.x, f1.y);
            ap2[ks] = pack_bf16x2(f2.x, f2.y);
            ap3[ks] = pack_bf16x2(f3.x, f3.y);
            Fh_lo[ks] = h ? f1 : f0;
            Fh_hi[ks] = h ? f3 : f2;
        }

        float* pbase = out + nd * 128 + h * 64 + q * 2;

        // ---- two N-passes: MMA (4 nt) -> epilogue -> RED ----
        #pragma unroll
        for (int pass = 0; pass < 2; pass++) {
            float acc[4][4];
            #pragma unroll
            for (int j = 0; j < 4; j++) {
                acc[j][0] = 0.f; acc[j][1] = 0.f; acc[j][2] = 0.f; acc[j][3] = 0.f;
            }
            #pragma unroll
            for (int ks = 0; ks < 4; ks++) {
                #pragma unroll
                for (int j = 0; j < 4; j++) {
                    const int m = pass * 4 + j;
                    asm volatile(
                        "mma.sync.aligned.m16n8k16.row.col.f32.bf16.bf16.f32 "
                        "{%0,%1,%2,%3}, {%4,%5,%6,%7}, {%8,%9}, {%0,%1,%2,%3};"
                        : "+f"(acc[j][0]), "+f"(acc[j][1]),
                          "+f"(acc[j][2]), "+f"(acc[j][3])
                        : "r"(ap0[ks]), "r"(ap1[ks]), "r"(ap2[ks]), "r"(ap3[ks]),
                          "r"(Breg[m][ks][0]), "r"(Breg[m][ks][1]));
                }
            }
            #pragma unroll
            for (int j = 0; j < 4; j++) {
                const int m  = pass * 4 + j;      // global nt; out col o = h*64 + m*8 + q*2
                const int ks = m >> 1;
                float2 eh = (m & 1) ? Fh_hi[ks] : Fh_lo[ks];      // fp32, patch h, col d
                unsigned int u0 = (m & 1) ? ap2[ks] : ap0[ks];    // packed patch0 @ d
                unsigned int u1 = (m & 1) ? ap3[ks] : ap1[ks];    // packed patch1 @ d
                float2 ge0 = h ? unpack_bf16x2(u0) : eh;          // gated e, patch0
                float2 ge1 = h ? eh : unpack_bf16x2(u1);          // gated e, patch1
                float sx = ge0.x * __saturatef(acc[j][0]) + ge1.x * __saturatef(acc[j][2]);
                float sy = ge0.y * __saturatef(acc[j][1]) + ge1.y * __saturatef(acc[j][3]);
                float vx = fmaf(lp, sx, eh.x);                    // pass-through fp32-exact
                float vy = fmaf(lp, sy, eh.y);
                if (valid) {
                    asm volatile("red.global.add.v2.f32 [%0], {%1, %2};"
                                 :: "l"(pbase + m * 8), "f"(vx), "f"(vy) : "memory");
                }
            }
        }
    }
}

// ---------------- launch ----------------
extern "C" void kernel_launch(void* const* d_in, const int* in_sizes, int n_in,
                              void* d_out, int out_size) {
    const float* x   = (const float*)d_in[0];
    const float* Wg  = (const float*)d_in[1];
    const float* lp  = (const float*)d_in[2];
    const void*  idx = d_in[3];

    long long E = (long long)in_sizes[0] / 128;
    int tiles = (int)((E + ROWS - 1) / ROWS);

    int dev = 0; cudaGetDevice(&dev);
    int sms = 148;
    cudaDeviceGetAttribute(&sms, cudaDevAttrMultiProcessorCount, dev);

    // prep: zero output + detect index dtype (single launch)
    int n4 = out_size / 4;
    long long npairs64 = E / 2; int npairs = npairs64 > 4096 ? 4096 : (int)npairs64;
    int zgrid = (n4 + 255) / 256;
    prep_kernel<<<zgrid, 256>>>((float4*)d_out, n4, (const unsigned int*)idx, npairs);

    size_t smem = (size_t)PAIRS * NBUF * SLOT * 4       // X rings
                + (size_t)PAIRS * NBUF * ROWS * 8;      // node rings
    cudaFuncSetAttribute(fused_gate_scatter,
                         cudaFuncAttributeMaxDynamicSharedMemorySize, (int)smem);
    int grid = 4 * sms;
    int maxg = (tiles + PAIRS - 1) / PAIRS;
    if (grid > maxg) grid = maxg;
    fused_gate_scatter<<<grid, THREADS, smem>>>(x, Wg, lp, idx, (float*)d_out, E, tiles);
}

// round 11
// speedup vs baseline: 2.7011x; 1.0876x over previous
#include <cuda_runtime.h>
#include <cuda_bf16.h>

#define THREADS 128
#define PAIRS 2                       // warp pairs per CTA
#define ROWS 8                        // edges per pair-tile
#define XPITCH 132                    // fp32 words per staged edge row (4-bank pad)
#define SLOT (ROWS * XPITCH)          // floats per slot (1056)
#define NBUF 4                        // ring slots per pair

__device__ int g_idx_is64;

static __device__ __forceinline__ unsigned int pack_bf16x2(float lo, float hi) {
    __nv_bfloat162 hh = __float22bfloat162_rn(make_float2(lo, hi));
    return *reinterpret_cast<unsigned int*>(&hh);
}
static __device__ __forceinline__ float2 unpack_bf16x2(unsigned int u) {
    float2 r;
    r.x = __uint_as_float(u << 16);
    r.y = __uint_as_float(u & 0xffff0000u);
    return r;
}

// ---------------- prep: zero output + detect index dtype ----------------
__global__ void prep_kernel(float4* out, int n4, const unsigned int* idxw, int n_pairs) {
    int i = blockIdx.x * blockDim.x + threadIdx.x;
    int stride = gridDim.x * blockDim.x;
    for (; i < n4; i += stride) out[i] = make_float4(0.f, 0.f, 0.f, 0.f);
    if (blockIdx.x == 0) {
        __shared__ unsigned int acc;
        if (threadIdx.x == 0) acc = 0u;
        __syncthreads();
        unsigned int v = 0u;
        for (int j = threadIdx.x; j < n_pairs; j += blockDim.x) v |= idxw[2 * j + 1];
        atomicOr(&acc, v);
        __syncthreads();
        if (threadIdx.x == 0) g_idx_is64 = (acc == 0u) ? 1 : 0;
    }
}

// ---------------- fused gate-GEMM + v4 register scatter ----------------
__global__ __launch_bounds__(THREADS, 4)
void fused_gate_scatter(const float* __restrict__ x,
                        const float* __restrict__ Wg,
                        const float* __restrict__ lparam,
                        const void* __restrict__ index,
                        float* __restrict__ out,
                        long long E, int num_tiles)
{
    extern __shared__ char smem_raw[];
    float* Xsm = reinterpret_cast<float*>(smem_raw);                 // [PAIRS][NBUF][ROWS][XPITCH]
    long long* Nsm = reinterpret_cast<long long*>(Xsm + PAIRS * NBUF * SLOT); // [PAIRS][NBUF][ROWS]

    const int tid  = threadIdx.x;
    const int wid  = tid >> 5;
    const int lane = tid & 31;
    const int g    = lane >> 2;      // 0..7 : edge row within pair-tile
    const int q    = lane & 3;       // 0..3
    const int pair = wid >> 1;       // 0..1
    const int h    = wid & 1;        // 0/1 : gate-col half

    const int   is64 = g_idx_is64;
    const float lp   = fabsf(__ldg(lparam));

    float* pairBuf = Xsm + pair * (NBUF * SLOT);
    long long* NsmP = Nsm + pair * (NBUF * ROWS);
    int* NsmP32 = reinterpret_cast<int*>(NsmP);

    // ---- persistent B fragments: cols n = h*64 + m*8 + g, m = 0..7 ----
    unsigned int Breg[8][4][2];
    #pragma unroll
    for (int m = 0; m < 8; m++) {
        const int n = h * 64 + m * 8 + g;
        #pragma unroll
        for (int ks = 0; ks < 4; ks++) {
            const int k = ks * 16 + q * 2;
            float2 w0 = __ldg(reinterpret_cast<const float2*>(Wg + n * 64 + k));
            float2 w1 = __ldg(reinterpret_cast<const float2*>(Wg + n * 64 + k + 8));
            Breg[m][ks][0] = pack_bf16x2(w0.x, w0.y);
            Breg[m][ks][1] = pack_bf16x2(w1.x, w1.y);
        }
    }

    const unsigned int xbuf_u32 = (unsigned int)__cvta_generic_to_shared(pairBuf);
    const unsigned int nbuf_u32 = (unsigned int)__cvta_generic_to_shared(NsmP);

    // stage one 8-edge tile-let into slot; warp h stages rows h*4 .. h*4+3
    auto stage = [&](int t, int slot) {
        const long long ebase = (long long)t * ROWS;
        #pragma unroll
        for (int p = 0; p < 4; p++) {
            const int row = h * 4 + p;
            long long e = ebase + row;
            if (e < E) {
                unsigned int dst = xbuf_u32 + (unsigned)((slot * SLOT + row * XPITCH + lane * 4) * 4);
                const float* src = x + e * 128 + lane * 4;
                asm volatile("cp.async.cg.shared.global [%0], [%1], 16;" :: "r"(dst), "l"(src));
            }
        }
        // index staging only for full tiles; tail handled by direct LDG at consume
        if (h == 0 && ebase + ROWS <= E) {
            if (is64) {
                if (lane < 4) {
                    unsigned int dst = nbuf_u32 + (unsigned)(slot * 64 + lane * 16);
                    const char* src = (const char*)index + ebase * 8 + lane * 16;
                    asm volatile("cp.async.ca.shared.global [%0], [%1], 16;" :: "r"(dst), "l"(src));
                }
            } else {
                if (lane < 2) {
                    unsigned int dst = nbuf_u32 + (unsigned)(slot * 64 + lane * 16);
                    const char* src = (const char*)index + ebase * 4 + lane * 16;
                    asm volatile("cp.async.ca.shared.global [%0], [%1], 16;" :: "r"(dst), "l"(src));
                }
            }
        }
    };

    const int S  = (int)gridDim.x * PAIRS;
    const int pg = (int)blockIdx.x * PAIRS + pair;

    // ---- prologue: prime NBUF-1 slots ----
    #pragma unroll
    for (int j = 0; j < NBUF - 1; j++) {
        int t = pg + j * S;
        if (t < num_tiles) stage(t, j);
        asm volatile("cp.async.commit_group;");
    }

    int c = 0;
    for (int tcur = pg; tcur < num_tiles; tcur += S, c++) {
        asm volatile("cp.async.wait_group %0;" :: "n"(NBUF - 2));     // own slot c complete
        asm volatile("bar.sync %0, 64;" :: "r"(pair + 1) : "memory"); // partner done with restage target
        int tpre = tcur + (NBUF - 1) * S;
        if (tpre < num_tiles) stage(tpre, (c + NBUF - 1) & (NBUF - 1));
        asm volatile("cp.async.commit_group;");

        const int slot = c & (NBUF - 1);
        const long long ebase = (long long)tcur * ROWS;
        const long long eg = ebase + g;
        const bool valid = (eg < E);
        const float* Xrow = pairBuf + slot * SLOT + g * XPITCH;

        long long nd = 0;
        if (valid) {
            if (ebase + ROWS <= E)
                nd = is64 ? NsmP[slot * ROWS + g]
                          : (long long)NsmP32[slot * ROWS * 2 + g];
            else
                nd = is64 ? ((const long long*)index)[eg]
                          : (long long)((const int*)index)[eg];
        }

        // ---- load + convert A; keep bf16 (both patches) + fp32 of patch h ----
        unsigned int ap0[4], ap1[4], ap2[4], ap3[4];   // packed bf16: p0@kb, p1@kb, p0@kb+8, p1@kb+8
        float2 Fh_lo[4], Fh_hi[4];                     // fp32 of patch h: cols kb, kb+8
        #pragma unroll
        for (int ks = 0; ks < 4; ks++) {
            const int kb = ks * 16 + q * 2;
            float2 f0 = *reinterpret_cast<const float2*>(Xrow + kb);
            float2 f1 = *reinterpret_cast<const float2*>(Xrow + 64 + kb);
            float2 f2 = *reinterpret_cast<const float2*>(Xrow + kb + 8);
            float2 f3 = *reinterpret_cast<const float2*>(Xrow + 64 + kb + 8);
            ap0[ks] = pack_bf16x2(f0.x, f0.y);
            ap1[ks] = pack_bf16x2(f1.x, f1.y);
            ap2[ks] = pack_bf16x2(f2.x, f2.y);
            ap3[ks] = pack_bf16x2(f3.x, f3.y);
            Fh_lo[ks] = h ? f1 : f0;
            Fh_hi[ks] = h ? f3 : f2;
        }

        float* nrow = out + nd * 128 + h * 64;

        // ---- two N-passes: MMA (4 m) -> epilogue -> quad-shuffle -> RED.v4 ----
        #pragma unroll
        for (int pass = 0; pass < 2; pass++) {
            float acc[4][4];
            #pragma unroll
            for (int j = 0; j < 4; j++) {
                acc[j][0] = 0.f; acc[j][1] = 0.f; acc[j][2] = 0.f; acc[j][3] = 0.f;
            }
            #pragma unroll
            for (int ks = 0; ks < 4; ks++) {
                #pragma unroll
                for (int j = 0; j < 4; j++) {
                    const int m = pass * 4 + j;
                    asm volatile(
                        "mma.sync.aligned.m16n8k16.row.col.f32.bf16.bf16.f32 "
                        "{%0,%1,%2,%3}, {%4,%5,%6,%7}, {%8,%9}, {%0,%1,%2,%3};"
                        : "+f"(acc[j][0]), "+f"(acc[j][1]),
                          "+f"(acc[j][2]), "+f"(acc[j][3])
                        : "r"(ap0[ks]), "r"(ap1[ks]), "r"(ap2[ks]), "r"(ap3[ks]),
                          "r"(Breg[m][ks][0]), "r"(Breg[m][ks][1]));
                }
            }
            // per-m final values
            float2 V[4];
            #pragma unroll
            for (int j = 0; j < 4; j++) {
                const int m  = pass * 4 + j;      // out col o = h*64 + m*8 + q*2
                const int ks = m >> 1;
                float2 eh = (m & 1) ? Fh_hi[ks] : Fh_lo[ks];      // fp32, patch h, col d
                unsigned int u0 = (m & 1) ? ap2[ks] : ap0[ks];    // packed patch0 @ d
                unsigned int u1 = (m & 1) ? ap3[ks] : ap1[ks];    // packed patch1 @ d
                float2 ge0 = h ? unpack_bf16x2(u0) : eh;          // gated e, patch0
                float2 ge1 = h ? eh : unpack_bf16x2(u1);          // gated e, patch1
                float sx = ge0.x * __saturatef(acc[j][0]) + ge1.x * __saturatef(acc[j][2]);
                float sy = ge0.y * __saturatef(acc[j][1]) + ge1.y * __saturatef(acc[j][3]);
                V[j].x = fmaf(lp, sx, eh.x);
                V[j].y = fmaf(lp, sy, eh.y);
            }
            // quad shuffle: build one v4 per thread per m-pair
            #pragma unroll
            for (int t2 = 0; t2 < 2; t2++) {
                const int j0 = 2 * t2, j1 = 2 * t2 + 1;
                // even q sends its m1 pair, odd q sends its m0 pair
                float2 mine = (q & 1) ? V[j0] : V[j1];
                float ox = __shfl_xor_sync(0xffffffffu, mine.x, 1);
                float oy = __shfl_xor_sync(0xffffffffu, mine.y, 1);
                // even q: own m0 pair (cols q*2) + partner m0 pair (cols q*2+2)
                // odd  q: partner m1 pair (cols (q-1)*2) + own m1 pair (cols q*2)
                float2 keep = (q & 1) ? V[j1] : V[j0];
                float vx0 = (q & 1) ? ox : keep.x;
                float vy0 = (q & 1) ? oy : keep.y;
                float vx1 = (q & 1) ? keep.x : ox;
                float vy1 = (q & 1) ? keep.y : oy;
                const int mm = pass * 4 + j0 + (q & 1);   // row this thread reduces
                const int cb = mm * 8 + (q >> 1) * 4;     // col base within half
                if (valid) {
                    asm volatile("red.global.add.v4.f32 [%0], {%1,%2,%3,%4};"
                                 :: "l"(nrow + cb), "f"(vx0), "f"(vy0), "f"(vx1), "f"(vy1)
                                 : "memory");
                }
            }
        }
    }
}

// ---------------- launch ----------------
extern "C" void kernel_launch(void* const* d_in, const int* in_sizes, int n_in,
                              void* d_out, int out_size) {
    const float* x   = (const float*)d_in[0];
    const float* Wg  = (const float*)d_in[1];
    const float* lp  = (const float*)d_in[2];
    const void*  idx = d_in[3];

    long long E = (long long)in_sizes[0] / 128;
    int tiles = (int)((E + ROWS - 1) / ROWS);

    int dev = 0; cudaGetDevice(&dev);
    int sms = 148;
    cudaDeviceGetAttribute(&sms, cudaDevAttrMultiProcessorCount, dev);

    // prep: zero output + detect index dtype (single launch)
    int n4 = out_size / 4;
    long long npairs64 = E / 2; int npairs = npairs64 > 4096 ? 4096 : (int)npairs64;
    int zgrid = (n4 + 255) / 256;
    prep_kernel<<<zgrid, 256>>>((float4*)d_out, n4, (const unsigned int*)idx, npairs);

    size_t smem = (size_t)PAIRS * NBUF * SLOT * 4       // X rings
                + (size_t)PAIRS * NBUF * ROWS * 8;      // node rings
    cudaFuncSetAttribute(fused_gate_scatter,
                         cudaFuncAttributeMaxDynamicSharedMemorySize, (int)smem);
    int grid = 4 * sms;
    int maxg = (tiles + PAIRS - 1) / PAIRS;
    if (grid > maxg) grid = maxg;
    fused_gate_scatter<<<grid, THREADS, smem>>>(x, Wg, lp, idx, (float*)d_out, E, tiles);
}